// round 2
// baseline (speedup 1.0000x reference)
#include <cuda_runtime.h>

#define N_ 16
#define C_ 64
#define H_ 64
#define W_ 64

// 16 MB scratch for t4 = -conv7x7(x, w4)   (static device array: allocation-free)
__device__ __align__(16) float g_t4[N_ * C_ * H_ * W_];

// ---------------------------------------------------------------------------
// Kernel 1: t4[n,co,h,w] = - sum_{ci,kh,kw} w4[co,ci,kh,kw] * x[n,ci,h+kh-3,w+kw-3]
// Tile: 64 co x (8h x 32w) per block, 256 threads, 8co x 8pix per thread.
// ---------------------------------------------------------------------------
#define TH 8
#define TW 32
#define SX_STRIDE 40   // 38 columns used; pad to keep 16B alignment of next array

__global__ __launch_bounds__(256, 2)
void conv7x7_kernel(const float* __restrict__ x, const float* __restrict__ w4)
{
    __shared__ __align__(16) float sx[14 * SX_STRIDE];   // (TH+6) x (TW+6), one ci
    __shared__ __align__(16) float sw[49 * 64];          // [kh*7+kw][co], negated

    const int n  = blockIdx.z;
    const int h0 = blockIdx.y * TH;
    const int w0 = blockIdx.x * TW;

    const int tid  = threadIdx.x;
    const int warp = tid >> 5;
    const int lane = tid & 31;
    const int co0  = warp * 8;          // 8 warps -> co groups of 8
    const int r_t  = lane >> 2;         // 0..7  (output row within tile)
    const int cb   = (lane & 3) * 8;    // 0,8,16,24 (output col base)

    float acc[8][8];
    #pragma unroll
    for (int j = 0; j < 8; j++)
        #pragma unroll
        for (int i = 0; i < 8; i++) acc[j][i] = 0.0f;

    const float* xn = x + n * (C_ * H_ * W_);

    for (int ci = 0; ci < C_; ci++) {
        // ---- stage x tile (zero-padded halo) ----
        const float* xc = xn + ci * (H_ * W_);
        for (int idx = tid; idx < 14 * 38; idx += 256) {
            int r = idx / 38, c = idx % 38;
            int gh = h0 + r - 3;
            int gw = w0 + c - 3;
            float v = 0.0f;
            if ((unsigned)gh < (unsigned)H_ && (unsigned)gw < (unsigned)W_)
                v = xc[gh * W_ + gw];
            sx[r * SX_STRIDE + c] = v;
        }
        // ---- stage weights for this ci, transposed to [k][co], negated ----
        for (int idx = tid; idx < 49 * 64; idx += 256) {
            int co = idx / 49, k = idx % 49;
            sw[k * 64 + co] = -w4[(co * 64 + ci) * 49 + k];
        }
        __syncthreads();

        // ---- FFMA main loop ----
        #pragma unroll 1
        for (int kh = 0; kh < 7; kh++) {
            const float* sxrow = &sx[(r_t + kh) * SX_STRIDE + cb];
            #pragma unroll
            for (int kw = 0; kw < 7; kw++) {
                const float4 wa = *(const float4*)&sw[(kh * 7 + kw) * 64 + co0];
                const float4 wb = *(const float4*)&sw[(kh * 7 + kw) * 64 + co0 + 4];
                float wv[8] = {wa.x, wa.y, wa.z, wa.w, wb.x, wb.y, wb.z, wb.w};
                float xv[8];
                #pragma unroll
                for (int i = 0; i < 8; i++) xv[i] = sxrow[kw + i];
                #pragma unroll
                for (int j = 0; j < 8; j++)
                    #pragma unroll
                    for (int i = 0; i < 8; i++)
                        acc[j][i] += wv[j] * xv[i];
            }
        }
        __syncthreads();
    }

    // ---- store t4 tile (vectorized) ----
    #pragma unroll
    for (int j = 0; j < 8; j++) {
        float* orow = g_t4 + ((n * C_ + co0 + j) * H_ + h0 + r_t) * W_ + w0 + cb;
        *(float4*)&orow[0] = make_float4(acc[j][0], acc[j][1], acc[j][2], acc[j][3]);
        *(float4*)&orow[4] = make_float4(acc[j][4], acc[j][5], acc[j][6], acc[j][7]);
    }
}

// ---------------------------------------------------------------------------
// Kernel 2: out[n,co,h,w] =
//    x[n,co,h,w] * ( w5[co,0]*t4[w-2] + w5[co,1]*t4[w] + w5[co,2]*t4[w+2] )
//  + sum_ci w8[co,ci] * x[n,ci,(h-1)%64,w]
// One block per (h, n). 256 threads: thread -> (co = t/4, 16-wide w chunk).
// ---------------------------------------------------------------------------
__global__ __launch_bounds__(256)
void fuse_kernel(const float* __restrict__ x, const float* __restrict__ w5,
                 const float* __restrict__ w8, float* __restrict__ out)
{
    __shared__ __align__(16) float sxr[64 * 64];   // rolled row: [ci][w]
    __shared__ __align__(16) float sw8[64 * 64];   // [co][ci]

    const int h  = blockIdx.x;
    const int n  = blockIdx.y;
    const int hr = (h + H_ - 1) & (H_ - 1);   // (h-1) mod 64
    const int tid = threadIdx.x;

    const float* xn = x + n * (C_ * H_ * W_);

    for (int idx = tid; idx < 64 * 64; idx += 256) {
        int ci = idx >> 6, w = idx & 63;
        sxr[idx] = xn[ci * (H_ * W_) + hr * W_ + w];
    }
    for (int idx = tid; idx < 64 * 64; idx += 256)
        sw8[idx] = w8[idx];
    __syncthreads();

    const int co = tid >> 2;
    const int wb = (tid & 3) * 16;

    float acc[16];
    #pragma unroll
    for (int i = 0; i < 16; i++) acc[i] = 0.0f;

    #pragma unroll 4
    for (int ci = 0; ci < 64; ci++) {
        float wv = sw8[co * 64 + ci];
        const float4* xr = (const float4*)&sxr[ci * 64 + wb];
        #pragma unroll
        for (int v = 0; v < 4; v++) {
            float4 xv = xr[v];
            acc[v * 4 + 0] += wv * xv.x;
            acc[v * 4 + 1] += wv * xv.y;
            acc[v * 4 + 2] += wv * xv.z;
            acc[v * 4 + 3] += wv * xv.w;
        }
    }

    // epilogue: depthwise(t4) * x + acc
    const float* xrow  = xn + co * (H_ * W_) + h * W_;
    const float* t4row = g_t4 + ((n * C_ + co) * H_ + h) * W_;
    float*       orow  = out + ((size_t)((n * C_ + co) * H_ + h)) * W_;
    const float a0 = w5[co * 3 + 0];
    const float a1 = w5[co * 3 + 1];
    const float a2 = w5[co * 3 + 2];

    #pragma unroll
    for (int i = 0; i < 16; i++) {
        int w = wb + i;
        float tm = (w >= 2)      ? t4row[w - 2] : 0.0f;
        float tc = t4row[w];
        float tp = (w < W_ - 2)  ? t4row[w + 2] : 0.0f;
        float t5 = a0 * tm + a1 * tc + a2 * tp;
        orow[w] = xrow[w] * t5 + acc[i];
    }
}

// ---------------------------------------------------------------------------
extern "C" void kernel_launch(void* const* d_in, const int* in_sizes, int n_in,
                              void* d_out, int out_size)
{
    const float* x  = (const float*)d_in[0];   // (16,64,64,64)
    const float* w4 = (const float*)d_in[1];   // (64,64,7,7)
    const float* w5 = (const float*)d_in[2];   // (64,1,1,3)
    const float* w8 = (const float*)d_in[3];   // (64,64,1,1)
    float* out = (float*)d_out;

    dim3 g1(W_ / TW, H_ / TH, N_);   // (2, 8, 16)
    conv7x7_kernel<<<g1, 256>>>(x, w4);

    dim3 g2(H_, N_);                 // (64, 16)
    fuse_kernel<<<g2, 256>>>(x, w5, w8, out);
}

// round 3
// speedup vs baseline: 1.0950x; 1.0950x over previous
#include <cuda_runtime.h>

#define N_ 16
#define C_ 64
#define H_ 64
#define W_ 64

typedef unsigned long long ull_t;

// 16 MB scratch for t4 = -conv7x7(x, w4)   (static device array: allocation-free)
__device__ __align__(16) float g_t4[N_ * C_ * H_ * W_];

// ---- f32x2 packed helpers (Blackwell) -------------------------------------
__device__ __forceinline__ void ffma2(ull_t& d, ull_t a, ull_t b) {
    asm("fma.rn.f32x2 %0, %1, %2, %0;" : "+l"(d) : "l"(a), "l"(b));
}
__device__ __forceinline__ ull_t bcast2(float v) {
    ull_t r; asm("mov.b64 %0, {%1, %1};" : "=l"(r) : "f"(v)); return r;
}
__device__ __forceinline__ void unpack2(ull_t v, float& lo, float& hi) {
    asm("mov.b64 {%0, %1}, %2;" : "=f"(lo), "=f"(hi) : "l"(v));
}

// ---------------------------------------------------------------------------
// Kernel 1: t4[n,co,h,w] = - sum_{ci,kh,kw} w4[co,ci,kh,kw] * x[n,ci,h+kh-3,w+kw-3]
// Tile: 64 co x (8h x 32w) per block, 256 threads, 8co x 8pix per thread.
// Accumulators packed f32x2 over adjacent co pairs.
// ---------------------------------------------------------------------------
#define TH 8
#define TW 32
#define SX_STRIDE 39   // 7r+8b+c mod 32 hits all 32 banks -> conflict-free

__global__ __launch_bounds__(256, 2)
void conv7x7_kernel(const float* __restrict__ x, const float* __restrict__ w4)
{
    __shared__ __align__(16) float sx[14 * SX_STRIDE];   // (TH+6) x (TW+6), one ci
    __shared__ __align__(16) float sw[49 * 64];          // [kh*7+kw][co], negated

    const int n  = blockIdx.z;
    const int h0 = blockIdx.y * TH;
    const int w0 = blockIdx.x * TW;

    const int tid  = threadIdx.x;
    const int warp = tid >> 5;
    const int lane = tid & 31;
    const int co0  = warp * 8;          // 8 warps -> co groups of 8
    const int r_t  = lane >> 2;         // 0..7  (output row within tile)
    const int cb   = (lane & 3) * 8;    // 0,8,16,24 (output col base)

    // acc2[j2][i] = (acc[co0+2*j2][i], acc[co0+2*j2+1][i]) packed
    ull_t acc2[4][8];
    #pragma unroll
    for (int j2 = 0; j2 < 4; j2++)
        #pragma unroll
        for (int i = 0; i < 8; i++) acc2[j2][i] = 0ULL;

    const float* xn = x + n * (C_ * H_ * W_);

    for (int ci = 0; ci < C_; ci++) {
        // ---- stage x tile (zero-padded halo) ----
        const float* xc = xn + ci * (H_ * W_);
        for (int idx = tid; idx < 14 * 38; idx += 256) {
            int r = idx / 38, c = idx % 38;
            int gh = h0 + r - 3;
            int gw = w0 + c - 3;
            float v = 0.0f;
            if ((unsigned)gh < (unsigned)H_ && (unsigned)gw < (unsigned)W_)
                v = xc[gh * W_ + gw];
            sx[r * SX_STRIDE + c] = v;
        }
        // ---- stage weights for this ci, transposed to [k][co], negated ----
        for (int idx = tid; idx < 49 * 64; idx += 256) {
            int co = idx / 49, k = idx % 49;
            sw[k * 64 + co] = -w4[(co * 64 + ci) * 49 + k];
        }
        __syncthreads();

        // ---- FFMA2 main loop ----
        #pragma unroll 1
        for (int kh = 0; kh < 7; kh++) {
            const float* sxrow = &sx[(r_t + kh) * SX_STRIDE + cb];
            // broadcast-pack the 14 x values this row needs (reused by all kw)
            ull_t xb[14];
            #pragma unroll
            for (int c = 0; c < 14; c++) xb[c] = bcast2(sxrow[c]);

            #pragma unroll
            for (int kw = 0; kw < 7; kw++) {
                const ull_t* wp = (const ull_t*)&sw[(kh * 7 + kw) * 64 + co0];
                ull_t w2[4] = { wp[0], wp[1], wp[2], wp[3] };  // co pairs, pre-packed
                #pragma unroll
                for (int j2 = 0; j2 < 4; j2++)
                    #pragma unroll
                    for (int i = 0; i < 8; i++)
                        ffma2(acc2[j2][i], w2[j2], xb[kw + i]);
            }
        }
        __syncthreads();
    }

    // ---- store t4 tile (unpack co pairs, vectorized stores) ----
    #pragma unroll
    for (int j2 = 0; j2 < 4; j2++) {
        float lo[8], hi[8];
        #pragma unroll
        for (int i = 0; i < 8; i++) unpack2(acc2[j2][i], lo[i], hi[i]);
        float* row0 = g_t4 + ((n * C_ + co0 + 2 * j2)     * H_ + h0 + r_t) * W_ + w0 + cb;
        float* row1 = g_t4 + ((n * C_ + co0 + 2 * j2 + 1) * H_ + h0 + r_t) * W_ + w0 + cb;
        *(float4*)&row0[0] = make_float4(lo[0], lo[1], lo[2], lo[3]);
        *(float4*)&row0[4] = make_float4(lo[4], lo[5], lo[6], lo[7]);
        *(float4*)&row1[0] = make_float4(hi[0], hi[1], hi[2], hi[3]);
        *(float4*)&row1[4] = make_float4(hi[4], hi[5], hi[6], hi[7]);
    }
}

// ---------------------------------------------------------------------------
// Kernel 2: out[n,co,h,w] =
//    x[n,co,h,w] * ( w5[co,0]*t4[w-2] + w5[co,1]*t4[w] + w5[co,2]*t4[w+2] )
//  + sum_ci w8[co,ci] * x[n,ci,(h-1)%64,w]
// One block per (h, n). Warp = 8 co rows, lane = w (coalesced epilogue).
// ---------------------------------------------------------------------------
#define SW8S 66   // transposed w8 stride: even (b64 align) and 2 mod 32 (mild conflicts)

__global__ __launch_bounds__(256)
void fuse_kernel(const float* __restrict__ x, const float* __restrict__ w5,
                 const float* __restrict__ w8, float* __restrict__ out)
{
    __shared__ __align__(16) float sxr[64 * 64];     // rolled row: [ci][w]
    __shared__ __align__(16) float sw8t[64 * SW8S];  // [ci][co]

    const int h  = blockIdx.x;
    const int n  = blockIdx.y;
    const int hr = (h + H_ - 1) & (H_ - 1);   // (h-1) mod 64
    const int tid = threadIdx.x;

    const float* xn = x + n * (C_ * H_ * W_);

    for (int idx = tid; idx < 64 * 64; idx += 256) {
        int ci = idx >> 6, w = idx & 63;
        sxr[idx] = xn[ci * (H_ * W_) + hr * W_ + w];
    }
    for (int idx = tid; idx < 64 * 64; idx += 256) {
        int co = idx >> 6, ci = idx & 63;                 // coalesced w8 read
        sw8t[ci * SW8S + co] = w8[co * 64 + ci];          // transposed store
    }
    __syncthreads();

    const int warp = tid >> 5;
    const int lane = tid & 31;
    const int co0  = warp * 8;

    // acc2[j2][v] = (t8[co0+2j2][w_v], t8[co0+2j2+1][w_v]),  w_v = lane + 32*v
    ull_t acc2[4][2];
    #pragma unroll
    for (int j2 = 0; j2 < 4; j2++) { acc2[j2][0] = 0ULL; acc2[j2][1] = 0ULL; }

    #pragma unroll 4
    for (int ci = 0; ci < 64; ci++) {
        ull_t xpa = bcast2(sxr[ci * 64 + lane]);
        ull_t xpb = bcast2(sxr[ci * 64 + lane + 32]);
        const ull_t* wp = (const ull_t*)&sw8t[ci * SW8S + co0];
        #pragma unroll
        for (int j2 = 0; j2 < 4; j2++) {
            ull_t w2 = wp[j2];
            ffma2(acc2[j2][0], w2, xpa);
            ffma2(acc2[j2][1], w2, xpb);
        }
    }

    // epilogue: out = x * depthwise(t4) + t8   (all lane-coalesced)
    #pragma unroll
    for (int j2 = 0; j2 < 4; j2++) {
        #pragma unroll
        for (int v = 0; v < 2; v++) {
            const int w = lane + 32 * v;
            float tlo, thi;
            unpack2(acc2[j2][v], tlo, thi);
            float tacc[2] = { tlo, thi };
            #pragma unroll
            for (int s = 0; s < 2; s++) {
                const int co = co0 + 2 * j2 + s;
                const float* t4row = g_t4 + ((n * C_ + co) * H_ + h) * W_;
                const float* xrow  = xn + co * (H_ * W_) + h * W_;
                float*       orow  = out + ((size_t)((n * C_ + co) * H_ + h)) * W_;
                const float a0 = w5[co * 3 + 0];
                const float a1 = w5[co * 3 + 1];
                const float a2 = w5[co * 3 + 2];
                float tm = (w >= 2)      ? t4row[w - 2] : 0.0f;
                float tc = t4row[w];
                float tp = (w < W_ - 2)  ? t4row[w + 2] : 0.0f;
                float t5 = a0 * tm + a1 * tc + a2 * tp;
                orow[w] = xrow[w] * t5 + tacc[s];
            }
        }
    }
}

// ---------------------------------------------------------------------------
extern "C" void kernel_launch(void* const* d_in, const int* in_sizes, int n_in,
                              void* d_out, int out_size)
{
    const float* x  = (const float*)d_in[0];   // (16,64,64,64)
    const float* w4 = (const float*)d_in[1];   // (64,64,7,7)
    const float* w5 = (const float*)d_in[2];   // (64,1,1,3)
    const float* w8 = (const float*)d_in[3];   // (64,64,1,1)
    float* out = (float*)d_out;

    dim3 g1(W_ / TW, H_ / TH, N_);   // (2, 8, 16)
    conv7x7_kernel<<<g1, 256>>>(x, w4);

    dim3 g2(H_, N_);                 // (64, 16)
    fuse_kernel<<<g2, 256>>>(x, w5, w8, out);
}

// round 6
// speedup vs baseline: 2.1709x; 1.9826x over previous
#include <cuda_runtime.h>
#include <cuda_bf16.h>

#define N_ 16
#define C_ 64
#define H_ 64
#define W_ 64

typedef __nv_bfloat16 bf16;

// ---- static device scratch (allocation-free) ------------------------------
__device__ __align__(16) float g_t4[N_ * C_ * H_ * W_];          // 16 MB
// transposed/split weights: [tap(49)][chunk(4)][co(64)][k(32: hi16|lo16)] bf16
__device__ __align__(16) bf16  g_wt[49 * 4 * 64 * 32];           // 784 KB

// ---- helpers --------------------------------------------------------------
__device__ __forceinline__ void cp_async16(unsigned dst, const void* src) {
    asm volatile("cp.async.cg.shared.global [%0], [%1], 16;" :: "r"(dst), "l"(src));
}
__device__ __forceinline__ void cp_commit() {
    asm volatile("cp.async.commit_group;");
}
template <int N>
__device__ __forceinline__ void cp_wait() {
    asm volatile("cp.async.wait_group %0;" :: "n"(N));
}

#define MMA_BF16(D, a0,a1,a2,a3, b0,b1)                                       \
    asm volatile("mma.sync.aligned.m16n8k16.row.col.f32.bf16.bf16.f32 "       \
        "{%0,%1,%2,%3}, {%4,%5,%6,%7}, {%8,%9}, {%0,%1,%2,%3};"               \
        : "+f"(D[0]), "+f"(D[1]), "+f"(D[2]), "+f"(D[3])                      \
        : "r"(a0), "r"(a1), "r"(a2), "r"(a3), "r"(b0), "r"(b1))

// ---------------------------------------------------------------------------
// Weight transpose/split/negate: g_wt[tap][chunk][co][k32] = bf16 split of -w4
// ---------------------------------------------------------------------------
__global__ void wtrans_kernel(const float* __restrict__ w4)
{
    int idx = blockIdx.x * 256 + threadIdx.x;
    if (idx >= 49 * 4 * 64 * 16) return;
    int cl    = idx & 15;
    int co    = (idx >> 4) & 63;
    int chunk = (idx >> 10) & 3;
    int tap   = idx >> 12;
    float v = -w4[co * 3136 + (chunk * 16 + cl) * 49 + tap];
    bf16 hi = __float2bfloat16(v);
    bf16 lo = __float2bfloat16(v - __bfloat162float(hi));
    bf16* t = g_wt + (size_t)(tap * 4 + chunk) * 2048;   // 64*32
    t[co * 32 + cl]      = hi;
    t[co * 32 + 16 + cl] = lo;
}

// ---------------------------------------------------------------------------
// Conv 7x7 via bf16 tensor cores (split-precision implicit GEMM).
// Block: 256 thr, out tile co64 x (1 row x 64 w) of one n. Grid (64, 16).
// SMEM (static, <48KB): halo[7 rows][70 w][k36 pad] + swt double buf [2][64][40].
// ---------------------------------------------------------------------------
#define HALO_PSTRIDE 36          // halves per pixel (32 payload + 4 pad)
#define HALO_HALVES  (7 * 70 * HALO_PSTRIDE)        // 17640
#define SWT_HALVES   (64 * 40)                      // 2560 per buffer
// total static smem: (17640 + 2*2560)*2 = 45520 bytes

__global__ __launch_bounds__(256)
void conv7x7_mma_kernel(const float* __restrict__ x)
{
    __shared__ __align__(16) bf16 halo[HALO_HALVES];
    __shared__ __align__(16) bf16 swt[2 * SWT_HALVES];

    const int tid    = threadIdx.x;
    const int warp   = tid >> 5;
    const int lane   = tid & 31;
    const int warp_m = warp >> 1;     // 0..3 : co slice of 16
    const int warp_h = warp & 1;      // 0..1 : w half (0..31 / 32..63)
    const int g      = lane >> 2;     // 0..7
    const int c      = lane & 3;      // 0..3

    const int n  = blockIdx.y;
    const int h0 = blockIdx.x;        // one output row per block

    float d[4][4];
    #pragma unroll
    for (int j = 0; j < 4; j++)
        #pragma unroll
        for (int k = 0; k < 4; k++) d[j][k] = 0.0f;

    const unsigned swt_u32_base = (unsigned)__cvta_generic_to_shared(swt);

    for (int chunk = 0; chunk < 4; chunk++) {
        // ---- zero halo (covers OOB rows + w borders) ----
        float4* hz = (float4*)halo;
        for (int i = tid; i < HALO_HALVES / 8; i += 256)
            hz[i] = make_float4(0.f, 0.f, 0.f, 0.f);
        __syncthreads();

        // ---- fill halo: rows h0-3 .. h0+3, split into bf16 hi/lo ----
        for (int i = tid; i < 7 * 64 * 16; i += 256) {
            int w  = i & 63;
            int cl = (i >> 6) & 15;
            int r  = i >> 10;              // 0..6
            int gh = h0 - 3 + r;
            if ((unsigned)gh < (unsigned)H_) {
                float v = x[((n * C_ + chunk * 16 + cl) * H_ + gh) * W_ + w];
                bf16 hi = __float2bfloat16(v);
                bf16 lo = __float2bfloat16(v - __bfloat162float(hi));
                int base = (r * 70 + w + 3) * HALO_PSTRIDE;
                halo[base + cl]      = hi;
                halo[base + 16 + cl] = lo;
            }
        }

        // ---- prefetch weights for tap 0 of this chunk into buf 0 ----
        {
            const char* src = (const char*)(g_wt + (size_t)(0 * 4 + chunk) * 2048);
            int co = tid >> 2, ch = tid & 3;
            cp_async16(swt_u32_base + (unsigned)(co * 80 + ch * 16),
                       src + co * 64 + ch * 16);
            cp_commit();
        }
        __syncthreads();   // halo visible

        int kh = 0, kw = 0;
        for (int tap = 0; tap < 49; tap++) {
            const int buf = tap & 1;

            if (tap < 48) {
                const char* src = (const char*)(g_wt + (size_t)((tap + 1) * 4 + chunk) * 2048);
                int co = tid >> 2, ch = tid & 3;
                cp_async16(swt_u32_base + (unsigned)((buf ^ 1) * SWT_HALVES * 2 + co * 80 + ch * 16),
                           src + co * 64 + ch * 16);
                cp_commit();
                cp_wait<1>();
            } else {
                cp_wait<0>();
            }
            __syncthreads();   // current weight buffer visible to all warps

            // ---- A fragments (weights, stride 40) ----
            const bf16* wb = swt + buf * SWT_HALVES;
            const int coA = warp_m * 16 + g;
            unsigned ah0 = *(const unsigned*)(wb + coA * 40 + 2 * c);
            unsigned ah1 = *(const unsigned*)(wb + (coA + 8) * 40 + 2 * c);
            unsigned ah2 = *(const unsigned*)(wb + coA * 40 + 2 * c + 8);
            unsigned ah3 = *(const unsigned*)(wb + (coA + 8) * 40 + 2 * c + 8);
            unsigned al0 = *(const unsigned*)(wb + coA * 40 + 16 + 2 * c);
            unsigned al1 = *(const unsigned*)(wb + (coA + 8) * 40 + 16 + 2 * c);
            unsigned al2 = *(const unsigned*)(wb + coA * 40 + 16 + 2 * c + 8);
            unsigned al3 = *(const unsigned*)(wb + (coA + 8) * 40 + 16 + 2 * c + 8);

            // ---- B fragments (shifted x window) + 3 split MMAs per n-tile ----
            const bf16* hb = halo + (kh * 70 + warp_h * 32 + g + kw) * HALO_PSTRIDE;
            #pragma unroll
            for (int j = 0; j < 4; j++) {
                const bf16* pb = hb + j * (8 * HALO_PSTRIDE);
                unsigned bh0 = *(const unsigned*)(pb + 2 * c);
                unsigned bh1 = *(const unsigned*)(pb + 2 * c + 8);
                unsigned bl0 = *(const unsigned*)(pb + 16 + 2 * c);
                unsigned bl1 = *(const unsigned*)(pb + 16 + 2 * c + 8);
                MMA_BF16(d[j], ah0, ah1, ah2, ah3, bh0, bh1);   // whi*xhi
                MMA_BF16(d[j], ah0, ah1, ah2, ah3, bl0, bl1);   // whi*xlo
                MMA_BF16(d[j], al0, al1, al2, al3, bh0, bh1);   // wlo*xhi
            }
            __syncthreads();   // all warps done with buf before it is overwritten

            if (++kw == 7) { kw = 0; ++kh; }
        }
    }

    // ---- store t4 tile ----
    #pragma unroll
    for (int j = 0; j < 4; j++) {
        int wcol = warp_h * 32 + j * 8 + 2 * c;
        #pragma unroll
        for (int s = 0; s < 2; s++) {
            int co = warp_m * 16 + g + s * 8;
            float2 v = make_float2(d[j][s * 2], d[j][s * 2 + 1]);
            *(float2*)&g_t4[((n * C_ + co) * H_ + h0) * W_ + wcol] = v;
        }
    }
}

// ---------------------------------------------------------------------------
// Kernel 2 (unchanged from R3): out = x * depthwise(t4) + w8 @ roll(x,1,H)
// ---------------------------------------------------------------------------
typedef unsigned long long ull_t;
__device__ __forceinline__ void ffma2(ull_t& d, ull_t a, ull_t b) {
    asm("fma.rn.f32x2 %0, %1, %2, %0;" : "+l"(d) : "l"(a), "l"(b));
}
__device__ __forceinline__ ull_t bcast2(float v) {
    ull_t r; asm("mov.b64 %0, {%1, %1};" : "=l"(r) : "f"(v)); return r;
}
__device__ __forceinline__ void unpack2(ull_t v, float& lo, float& hi) {
    asm("mov.b64 {%0, %1}, %2;" : "=f"(lo), "=f"(hi) : "l"(v));
}

#define SW8S 66

__global__ __launch_bounds__(256)
void fuse_kernel(const float* __restrict__ x, const float* __restrict__ w5,
                 const float* __restrict__ w8, float* __restrict__ out)
{
    __shared__ __align__(16) float sxr[64 * 64];
    __shared__ __align__(16) float sw8t[64 * SW8S];

    const int h  = blockIdx.x;
    const int n  = blockIdx.y;
    const int hr = (h + H_ - 1) & (H_ - 1);
    const int tid = threadIdx.x;

    const float* xn = x + n * (C_ * H_ * W_);

    for (int idx = tid; idx < 64 * 64; idx += 256) {
        int ci = idx >> 6, w = idx & 63;
        sxr[idx] = xn[ci * (H_ * W_) + hr * W_ + w];
    }
    for (int idx = tid; idx < 64 * 64; idx += 256) {
        int co = idx >> 6, ci = idx & 63;
        sw8t[ci * SW8S + co] = w8[co * 64 + ci];
    }
    __syncthreads();

    const int warp = tid >> 5;
    const int lane = tid & 31;
    const int co0  = warp * 8;

    ull_t acc2[4][2];
    #pragma unroll
    for (int j2 = 0; j2 < 4; j2++) { acc2[j2][0] = 0ULL; acc2[j2][1] = 0ULL; }

    #pragma unroll 4
    for (int ci = 0; ci < 64; ci++) {
        ull_t xpa = bcast2(sxr[ci * 64 + lane]);
        ull_t xpb = bcast2(sxr[ci * 64 + lane + 32]);
        const ull_t* wp = (const ull_t*)&sw8t[ci * SW8S + co0];
        #pragma unroll
        for (int j2 = 0; j2 < 4; j2++) {
            ull_t w2 = wp[j2];
            ffma2(acc2[j2][0], w2, xpa);
            ffma2(acc2[j2][1], w2, xpb);
        }
    }

    #pragma unroll
    for (int j2 = 0; j2 < 4; j2++) {
        #pragma unroll
        for (int v = 0; v < 2; v++) {
            const int w = lane + 32 * v;
            float tlo, thi;
            unpack2(acc2[j2][v], tlo, thi);
            float tacc[2] = { tlo, thi };
            #pragma unroll
            for (int s = 0; s < 2; s++) {
                const int co = co0 + 2 * j2 + s;
                const float* t4row = g_t4 + ((n * C_ + co) * H_ + h) * W_;
                const float* xrow  = xn + co * (H_ * W_) + h * W_;
                float*       orow  = out + ((size_t)((n * C_ + co) * H_ + h)) * W_;
                const float a0 = w5[co * 3 + 0];
                const float a1 = w5[co * 3 + 1];
                const float a2 = w5[co * 3 + 2];
                float tm = (w >= 2)      ? t4row[w - 2] : 0.0f;
                float tc = t4row[w];
                float tp = (w < W_ - 2)  ? t4row[w + 2] : 0.0f;
                float t5 = a0 * tm + a1 * tc + a2 * tp;
                orow[w] = xrow[w] * t5 + tacc[s];
            }
        }
    }
}

// ---------------------------------------------------------------------------
extern "C" void kernel_launch(void* const* d_in, const int* in_sizes, int n_in,
                              void* d_out, int out_size)
{
    const float* x  = (const float*)d_in[0];   // (16,64,64,64)
    const float* w4 = (const float*)d_in[1];   // (64,64,7,7)
    const float* w5 = (const float*)d_in[2];   // (64,1,1,3)
    const float* w8 = (const float*)d_in[3];   // (64,64,1,1)
    float* out = (float*)d_out;

    wtrans_kernel<<<784, 256>>>(w4);

    dim3 g1(H_, N_);                 // (64, 16)
    conv7x7_mma_kernel<<<g1, 256>>>(x);

    dim3 g2(H_, N_);                 // (64, 16)
    fuse_kernel<<<g2, 256>>>(x, w5, w8, out);
}